// round 7
// baseline (speedup 1.0000x reference)
#include <cuda_runtime.h>
#include <cstdint>

// Problem constants
#define N_IMG 16384
#define SS 49
#define NCELL (N_IMG * SS)              // 802816
#define F 30
#define CPC 64                          // cells per chunk
#define NCHUNK (NCELL / CPC)            // 12544
#define THREADS 128                     // 2 threads per cell (pair-split)
#define BLKS_PER_SM 6
#define GRID (BLKS_PER_SM * 148)        // 888
#define STAGES 2

#define CHUNK_FLOATS (CPC * F)          // 1920 floats per tensor
#define CHUNK_BYTES (CHUNK_FLOATS * 4)  // 7680 B per tensor
#define TX_BYTES (2 * CHUNK_BYTES)      // 15360 B per chunk
#define DYN_SMEM (STAGES * TX_BYTES)    // 30720 B

__device__ float g_partial[GRID];
__device__ unsigned int g_count;        // zero at load; last block resets each run
__device__ unsigned int g_ticket;       // dynamic chunk scheduler; reset each run

__device__ __forceinline__ uint32_t smem_u32(const void* p) {
    return (uint32_t)__cvta_generic_to_shared(p);
}

#define MBAR_WAIT(bar, parity) do {                                           \
    asm volatile(                                                             \
        "{\n\t.reg .pred P1;\n\t"                                             \
        "WAIT_%=:\n\t"                                                        \
        "mbarrier.try_wait.parity.acquire.cta.shared::cta.b64 P1, [%0], %1, 0x989680;\n\t" \
        "@P1 bra.uni DONE_%=;\n\t"                                            \
        "bra.uni WAIT_%=;\n\t"                                                \
        "DONE_%=:\n\t}"                                                       \
        :: "r"(bar), "r"(parity) : "memory");                                 \
} while (0)

__global__ __launch_bounds__(THREADS) void loss_kernel(
        const float* __restrict__ preds,
        const float* __restrict__ targets,
        float* __restrict__ out) {
    extern __shared__ float smem[];     // [STAGES][preds 1920 | targets 1920]
    __shared__ __align__(8) unsigned long long mbar[STAGES];
    __shared__ int s_chunk[STAGES];
    __shared__ float warp_sums[THREADS / 32];
    __shared__ double dsum[THREADS / 32];
    __shared__ bool is_last;

    const int tid = threadIdx.x;
    const int part = tid & 1;           // 0: classes 0-9 + box0; 1: classes 10-19 + box1
    const int cell = tid >> 1;          // 0..63 within chunk

    if (tid == 0) {
#pragma unroll
        for (int s = 0; s < STAGES; s++)
            asm volatile("mbarrier.init.shared.b64 [%0], 1;"
                         :: "r"(smem_u32(&mbar[s])) : "memory");
    }
    __syncthreads();

    auto issue = [&](int c, int buf) {
        uint32_t bar = smem_u32(&mbar[buf]);
        asm volatile("mbarrier.arrive.expect_tx.shared.b64 _, [%0], %1;"
                     :: "r"(bar), "r"((uint32_t)TX_BYTES) : "memory");
        uint32_t dstp = smem_u32(smem) + buf * TX_BYTES;
        uint32_t dstt = dstp + CHUNK_BYTES;
        const float* srcp = preds + (long long)c * CHUNK_FLOATS;
        const float* srct = targets + (long long)c * CHUNK_FLOATS;
        asm volatile("cp.async.bulk.shared::cta.global.mbarrier::complete_tx::bytes [%0], [%1], %2, [%3];"
                     :: "r"(dstp), "l"(srcp), "r"((uint32_t)CHUNK_BYTES), "r"(bar) : "memory");
        asm volatile("cp.async.bulk.shared::cta.global.mbarrier::complete_tx::bytes [%0], [%1], %2, [%3];"
                     :: "r"(dstt), "l"(srct), "r"((uint32_t)CHUNK_BYTES), "r"(bar) : "memory");
    };

    // Prologue: grab and issue one chunk per stage.
    if (tid == 0) {
#pragma unroll
        for (int s = 0; s < STAGES; s++) {
            int c = (int)atomicAdd(&g_ticket, 1u);
            s_chunk[s] = c;
            if (c < NCHUNK) issue(c, s);
        }
    }
    __syncthreads();

    float l = 0.0f;
    int buf = 0, phs = 0;
    for (;;) {
        const int c = s_chunk[buf];
        if (c >= NCHUNK) break;
        MBAR_WAIT(smem_u32(&mbar[buf]), phs);

        // Cell record as float2 (15 float2 per cell per tensor).
        const float2* p2 = (const float2*)(smem + buf * 2 * CHUNK_FLOATS + cell * F);
        const float2* t2 = (const float2*)((const float*)p2 + CHUNK_FLOATS);

        const float2 pc = p2[10];
        const float2 tc = t2[10];
        const bool obj = tc.x > 0.0f;

        // conf term (once per cell -> part 0); t[21] == t[20].
        if (part == 0) {
            float d0 = pc.x - tc.x, d1 = pc.y - tc.y;
            l += 0.5f * (d0 * d0 + d1 * d1);
        }

        const unsigned omask = __ballot_sync(0xffffffffu, obj);

        if (obj) {
            // my half of the class probs (float2 idx 5*part .. 5*part+4)
            float acc = 0.0f;
#pragma unroll
            for (int j = 0; j < 5; j++) {
                float2 a = p2[5 * part + j], b = t2[5 * part + j];
                float dx = a.x - b.x, dy = a.y - b.y;
                acc += dx * dx + dy * dy;
            }
            l += acc;

            // my box IoU (box `part`)
            float2 pxy = p2[11 + 2 * part], pwh = p2[12 + 2 * part];
            float2 txy = t2[11 + 2 * part], twh = t2[12 + 2 * part];
            float xA = fmaxf(pxy.x - pwh.x * 0.5f, txy.x - twh.x * 0.5f);
            float yA = fmaxf(pxy.y - pwh.y * 0.5f, txy.y - twh.y * 0.5f);
            float xB = fminf(pxy.x + pwh.x * 0.5f, txy.x + twh.x * 0.5f);
            float yB = fminf(pxy.y + pwh.y * 0.5f, txy.y + twh.y * 0.5f);
            float inter = fmaxf(0.0f, xB - xA) * fmaxf(0.0f, yB - yA);
            float iou_mine = inter / (pwh.x * pwh.y + twh.x * twh.y - inter);

            // exchange with partner lane (same cell, both in omask)
            float iou_other = __shfl_xor_sync(omask, iou_mine, 1);
            float iou0 = part ? iou_other : iou_mine;
            float iou1 = part ? iou_mine : iou_other;
            int best = (iou1 > iou0) ? 1 : 0;   // argmax, tie -> 0

            // responsible-conf term (once per cell -> part 0)
            if (part == 0) {
                float pcv = best ? pc.y : pc.x;
                float dc = pcv - 1.0f;
                l += 0.5f * dc * dc;
            }

            // coord term: computed by the part that owns the best box
            if (best == part) {
                float dx = pxy.x - txy.x;
                float dy = pxy.y - txy.y;
                float dw = sqrtf(pwh.x) - sqrtf(twh.x);
                float dh = sqrtf(pwh.y) - sqrtf(twh.y);
                l += 5.0f * (dx * dx + dy * dy + dw * dw + dh * dh);
            }
        }

        __syncthreads();   // everyone done reading stage `buf`

        if (tid == 0) {    // grab next chunk and refill this stage
            int cn = (int)atomicAdd(&g_ticket, 1u);
            s_chunk[buf] = cn;
            if (cn < NCHUNK) issue(cn, buf);
        }

        if (++buf == STAGES) { buf = 0; phs ^= 1; }
    }

    // Intra-block reduction.
#pragma unroll
    for (int off = 16; off > 0; off >>= 1)
        l += __shfl_down_sync(0xffffffffu, l, off);
    if ((tid & 31) == 0)
        warp_sums[tid >> 5] = l;
    __syncthreads();

    if (tid == 0) {
        float blk = warp_sums[0] + warp_sums[1] + warp_sums[2] + warp_sums[3];
        g_partial[blockIdx.x] = blk;
        __threadfence();
        unsigned int old = atomicAdd(&g_count, 1u);
        is_last = (old == GRID - 1);
    }
    __syncthreads();

    if (is_last) {
        double acc = 0.0;
        for (int i = tid; i < GRID; i += THREADS)
            acc += (double)__ldcg(&g_partial[i]);
#pragma unroll
        for (int off = 16; off > 0; off >>= 1)
            acc += __shfl_down_sync(0xffffffffu, acc, off);
        if ((tid & 31) == 0)
            dsum[tid >> 5] = acc;
        __syncthreads();
        if (tid == 0) {
            double total = dsum[0] + dsum[1] + dsum[2] + dsum[3];
            out[0] = (float)(total / (double)N_IMG);
            __threadfence();
            g_count = 0;
            g_ticket = 0;   // reset scheduler for next graph replay
        }
    }
}

extern "C" void kernel_launch(void* const* d_in, const int* in_sizes, int n_in,
                              void* d_out, int out_size) {
    const float* preds = (const float*)d_in[0];
    const float* targets = (const float*)d_in[1];
    float* out = (float*)d_out;

    cudaFuncSetAttribute(loss_kernel, cudaFuncAttributeMaxDynamicSharedMemorySize, DYN_SMEM);
    loss_kernel<<<GRID, THREADS, DYN_SMEM>>>(preds, targets, out);
}